// round 16
// baseline (speedup 1.0000x reference)
#include <cuda_runtime.h>
#include <math.h>
#include <stdint.h>

#define B_ 4
#define L_ 4096
#define D_ 1024
#define R_ 16
#define PLU_ 120
#define PLUP_ 128
#define GEO_ 256
#define BL_ 16384
#define MROWS_ (6 * BL_)
#define EPS_ 1e-6f

// Scratch (static device globals: allocation-free)
__device__ float d_Z[BL_ * R_];                  // (B*L, 16)
__device__ float d_S[BL_ * GEO_];                // (B*L, 256)
__device__ float d_P[(size_t)MROWS_ * PLUP_];    // plucker rows (cols 120..127 = 0)
__device__ float d_G[(size_t)BL_ * D_];          // g (raw fp32)
__device__ float d_G1p[PLUP_ * GEO_];            // repacked g1_w (fragment order)
__device__ float d_W2p[GEO_ * D_];               // repacked g2_w
__device__ float d_Wgp[2 * D_ * D_];             // repacked gate_w
__device__ float d_RwT[R_ * D_];                 // red_w transposed [16][1024]

__constant__ int c_off[6] = {1, 2, 4, 8, 16, 32};

__device__ __forceinline__ uint32_t smem_u32(const void* p) {
    uint32_t a;
    asm("{ .reg .u64 t; cvta.to.shared.u64 t, %1; cvt.u32.u64 %0, t; }"
        : "=r"(a) : "l"(p));
    return a;
}
__device__ __forceinline__ void cp16(uint32_t s, const void* g) {
    asm volatile("cp.async.cg.shared.global [%0], [%1], 16;" :: "r"(s), "l"(g));
}
__device__ __forceinline__ void cp_commit() { asm volatile("cp.async.commit_group;"); }
template <int N>
__device__ __forceinline__ void cp_wait() {
    asm volatile("cp.async.wait_group %0;" :: "n"(N));
}
__device__ __forceinline__ void ldsm4(uint32_t* r, uint32_t addr) {
    asm volatile("ldmatrix.sync.aligned.m8n8.x4.shared.b16 {%0,%1,%2,%3}, [%4];"
                 : "=r"(r[0]), "=r"(r[1]), "=r"(r[2]), "=r"(r[3]) : "r"(addr));
}
__device__ __forceinline__ void mma_tf32(float* d, const uint32_t* a,
                                         uint32_t b0, uint32_t b1) {
    asm volatile(
        "mma.sync.aligned.m16n8k8.row.col.f32.tf32.tf32.f32 "
        "{%0,%1,%2,%3}, {%4,%5,%6,%7}, {%8,%9}, {%0,%1,%2,%3};"
        : "+f"(d[0]), "+f"(d[1]), "+f"(d[2]), "+f"(d[3])
        : "r"(a[0]), "r"(a[1]), "r"(a[2]), "r"(a[3]), "r"(b0), "r"(b1));
}
__device__ __forceinline__ float gelu_exact(float x) {
    return 0.5f * x * (1.f + erff(x * 0.7071067811865476f));
}
__device__ __forceinline__ int count_of(int l) {
    return (l >= 1) + (l >= 2) + (l >= 4) + (l >= 8) + (l >= 16) + (l >= 32);
}

// ---------------- transpose red_w -> d_RwT[16][1024] ----------------
__global__ void k_rwT(const float* __restrict__ rw) {
    int i = blockIdx.x * 256 + threadIdx.x;   // 16384
    int d = i >> 4, r = i & 15;
    d_RwT[r * D_ + d] = rw[d * R_ + r];
}

// ------- z = h @ red_w + red_b (warp per token, 4 tokens/warp) -------
__global__ void k_z2(const float* __restrict__ h, const float* __restrict__ rb) {
    extern __shared__ float rwT[];            // 64KB
    int tid = threadIdx.x, wid = tid >> 5, lane = tid & 31;
    for (int i = tid * 4; i < R_ * D_; i += 1024)
        *reinterpret_cast<float4*>(rwT + i) =
            *reinterpret_cast<const float4*>(d_RwT + i);
    __syncthreads();

    #pragma unroll 1
    for (int tt = 0; tt < 4; ++tt) {
        int t = blockIdx.x * 32 + wid * 4 + tt;
        float acc[16];
        #pragma unroll
        for (int r = 0; r < 16; ++r) acc[r] = 0.f;
        const float* hrow = h + (size_t)t * D_;
        #pragma unroll
        for (int it = 0; it < 8; ++it) {
            float4 hv = *reinterpret_cast<const float4*>(hrow + it * 128 + lane * 4);
            #pragma unroll
            for (int r = 0; r < 16; ++r) {
                float4 wv = *reinterpret_cast<const float4*>(
                    rwT + r * D_ + it * 128 + lane * 4);
                acc[r] += hv.x * wv.x + hv.y * wv.y + hv.z * wv.z + hv.w * wv.w;
            }
        }
        #pragma unroll
        for (int r = 0; r < 16; ++r)
            #pragma unroll
            for (int o = 16; o > 0; o >>= 1)
                acc[r] += __shfl_xor_sync(0xffffffffu, acc[r], o);
        if (lane == 0) {
            #pragma unroll
            for (int r = 0; r < 16; ++r) d_Z[t * R_ + r] = acc[r] + rb[r];
        }
    }
}

// ------ repack weight [K][N] -> fragment order [K/16][N/8][lane][slot] ------
__global__ void k_repack(const float* __restrict__ src, float* __restrict__ dst,
                         int N, int NB, int Kvalid) {
    __shared__ float tile[16 * 132];
    int tid = threadIdx.x;
    int k0 = blockIdx.y * 16;
    int n0 = blockIdx.x * 128;
    #pragma unroll
    for (int p = 0; p < 8; ++p) {
        int idx = tid + p * 256;              // 2048 = 16 x 128
        int kr = idx >> 7, nn = idx & 127;
        tile[kr * 132 + nn] = (k0 + kr < Kvalid)
            ? src[(size_t)(k0 + kr) * N + n0 + nn] : 0.f;
    }
    __syncthreads();
    size_t base = ((size_t)blockIdx.y * NB + (n0 >> 3)) * 128;
    #pragma unroll
    for (int p = 0; p < 8; ++p) {
        int idx = tid + p * 256;
        int s = idx & 3;
        int l = (idx >> 2) & 31;
        int nbL = idx >> 7;
        int kr = ((s >> 1) << 3) + (l & 3) + ((s & 1) << 2);
        int nn = nbL * 8 + (l >> 2);
        dst[base + idx] = tile[kr * 132 + nn];
    }
}

// ---------------- plucker rows: d_P[di*BL + t][0:128] ----------------
__global__ void k_plucker() {
    int wid = threadIdx.x >> 5, lane = threadIdx.x & 31;
    int ridx = blockIdx.x * 8 + wid;
    int di = ridx / BL_;
    int t = ridx - di * BL_;
    int l = t & (L_ - 1);
    int delta = c_off[di];
    float* dst = d_P + (size_t)ridx * PLUP_;
    if (l < delta) {                       // warp-uniform branch
        #pragma unroll
        for (int q = 0; q < 4; ++q) dst[lane + q * 32] = 0.f;
        return;
    }
    int tp = t - delta;
    float w = (lane < 16) ? d_Z[tp * R_ + lane] : d_Z[t * R_ + lane - 16];
    float p[4];
    float sq = 0.f;
    #pragma unroll
    for (int q = 0; q < 4; ++q) {
        int k = lane + q * 32;
        int kc = (k < PLU_) ? k : 0;
        int kk = kc, i = 0, len = R_ - 1;
        while (kk >= len) { kk -= len; i++; len--; }
        int j = i + 1 + kk;
        float ui = __shfl_sync(0xffffffffu, w, i);
        float uj = __shfl_sync(0xffffffffu, w, j);
        float vi = __shfl_sync(0xffffffffu, w, 16 + i);
        float vj = __shfl_sync(0xffffffffu, w, 16 + j);
        float val = (k < PLU_) ? (ui * vj - uj * vi) : 0.f;
        p[q] = val;
        sq += val * val;
    }
    #pragma unroll
    for (int o = 16; o > 0; o >>= 1) sq += __shfl_xor_sync(0xffffffffu, sq, o);
    float inv = 1.f / fmaxf(sqrtf(sq), EPS_);
    #pragma unroll
    for (int q = 0; q < 4; ++q) dst[lane + q * 32] = p[q] * inv;
}

// ====== k_geom_gemm: d_S[t] = sum_di masked gelu(P_di[t] @ g1w + g1b) ======
// Tile 128 tokens x 64 N. Warp 32x32 (4x2 grid). di-loop in registers, no atomics.
// 3-stage cp.async, single barrier per iter.
#define GLDA 36
#define GA_F (128 * GLDA)               // 4608
#define GB_F 2048                       // 2 slices x 8 nb x 128
#define GSTAGE_F (GA_F + GB_F)          // 6656
#define SMEM_GEOM (3 * GSTAGE_F * 4)    // 79872 bytes

__global__ void __launch_bounds__(256, 2) k_geom_gemm(const float* __restrict__ Bp,
                                                      const float* __restrict__ bias) {
    extern __shared__ __align__(128) float sm[];
    constexpr int NB_TOT = GEO_ / 8;    // 32
    constexpr int GNIT = 24;            // 6 deltas x 4 k-iters

    const int tid = threadIdx.x;
    const int wid = tid >> 5, lane = tid & 31;
    const int wm = wid >> 1, wn = wid & 1;   // 4 x 2: warp tile 32 x 32
    const int m0 = blockIdx.y * 128;         // token rows
    const int n0 = blockIdx.x * 64;
    const uint32_t smb = smem_u32(sm);

    const int lrow = (lane & 7) + ((lane >> 3) & 1) * 8;
    const int lcol = (lane >> 4) * 4;
    const int g = lane >> 2, t4 = lane & 3;

    float acc[2][4][4], sum[2][4][4];
    #pragma unroll
    for (int i = 0; i < 2; ++i)
        #pragma unroll
        for (int nb = 0; nb < 4; ++nb)
            #pragma unroll
            for (int q = 0; q < 4; ++q) { acc[i][nb][q] = 0.f; sum[i][nb][q] = 0.f; }

    // bias registers (per fragment column)
    float br[4][4];
    #pragma unroll
    for (int nb = 0; nb < 4; ++nb) {
        int n = n0 + wn * 32 + nb * 8 + t4 * 2;
        br[nb][0] = bias[n];     br[nb][1] = bias[n + 1];
        br[nb][2] = br[nb][0];   br[nb][3] = br[nb][1];
    }

    auto load_async = [&](int gi, int s) {
        const int di = gi >> 2, it = gi & 3;
        const int k0 = it * 32;
        const uint32_t aoff = s * GSTAGE_F;
        const uint32_t boff = s * GSTAGE_F + GA_F;
        #pragma unroll
        for (int p = 0; p < 4; ++p) {
            int idx = tid + p * 256;
            int row = idx >> 3, c4 = idx & 7;
            cp16(smb + (aoff + row * GLDA + c4 * 4) * 4,
                 d_P + ((size_t)di * BL_ + m0 + row) * PLUP_ + k0 + c4 * 4);
        }
        const float* bsrc = Bp + ((size_t)(k0 >> 4) * NB_TOT + (n0 >> 3)) * 128;
        #pragma unroll
        for (int p = 0; p < 2; ++p) {
            int idx = tid + p * 256;            // 512 float4
            int slice = idx >> 8, pos = idx & 255;
            cp16(smb + (boff + idx * 4) * 4,
                 bsrc + (size_t)slice * NB_TOT * 128 + pos * 4);
        }
        cp_commit();
    };

    auto compute = [&](int s) {
        const float* Bs = sm + s * GSTAGE_F + GA_F;
        const uint32_t abase = smb + (s * GSTAGE_F) * 4;
        #pragma unroll
        for (int kb2s = 0; kb2s < 2; ++kb2s) {
            uint32_t a[2][2][4];
            #pragma unroll
            for (int i = 0; i < 2; ++i)
                #pragma unroll
                for (int kss = 0; kss < 2; ++kss) {
                    int ks = kb2s * 2 + kss;
                    ldsm4(a[i][kss],
                          abase + ((wm * 32 + i * 16 + lrow) * GLDA + ks * 8 + lcol) * 4);
                }
            #pragma unroll
            for (int nb = 0; nb < 4; ++nb) {
                float4 b4 = *reinterpret_cast<const float4*>(
                    Bs + kb2s * 1024 + (wn * 4 + nb) * 128 + lane * 4);
                uint32_t b0 = __float_as_uint(b4.x), b1 = __float_as_uint(b4.y);
                uint32_t b2 = __float_as_uint(b4.z), b3 = __float_as_uint(b4.w);
                #pragma unroll
                for (int i = 0; i < 2; ++i) {
                    mma_tf32(acc[i][nb], a[i][0], b0, b1);
                    mma_tf32(acc[i][nb], a[i][1], b2, b3);
                }
            }
        }
    };

    load_async(0, 0);
    load_async(1, 1);
    #pragma unroll 1
    for (int gi = 0; gi < GNIT; ++gi) {
        if (gi == GNIT - 1) cp_wait<0>(); else cp_wait<1>();
        __syncthreads();
        if (gi + 2 < GNIT) load_async(gi + 2, (gi + 2) % 3);
        compute(gi % 3);
        if ((gi & 3) == 3) {       // finished one delta: fold into sum
            int di = gi >> 2;
            int delta = c_off[di];
            #pragma unroll
            for (int i = 0; i < 2; ++i)
                #pragma unroll
                for (int half = 0; half < 2; ++half) {
                    int trow = m0 + wm * 32 + i * 16 + g + half * 8;
                    bool on = (trow & (L_ - 1)) >= delta;
                    #pragma unroll
                    for (int nb = 0; nb < 4; ++nb) {
                        if (on) {
                            sum[i][nb][half * 2 + 0] +=
                                gelu_exact(acc[i][nb][half * 2 + 0] + br[nb][half * 2 + 0]);
                            sum[i][nb][half * 2 + 1] +=
                                gelu_exact(acc[i][nb][half * 2 + 1] + br[nb][half * 2 + 1]);
                        }
                        acc[i][nb][half * 2 + 0] = 0.f;
                        acc[i][nb][half * 2 + 1] = 0.f;
                    }
                }
        }
    }

    // Store d_S (unnormalized gelu-sum; /count folded into next GEMM's epilogue)
    #pragma unroll
    for (int i = 0; i < 2; ++i)
        #pragma unroll
        for (int half = 0; half < 2; ++half) {
            int trow = m0 + wm * 32 + i * 16 + g + half * 8;
            float* srow = d_S + (size_t)trow * GEO_;
            #pragma unroll
            for (int nb = 0; nb < 4; ++nb) {
                int n = n0 + wn * 32 + nb * 8 + t4 * 2;
                *reinterpret_cast<float2*>(srow + n) =
                    make_float2(sum[i][nb][half * 2 + 0], sum[i][nb][half * 2 + 1]);
            }
        }
}

// ====== explicit-mma tf32 GEMM: block 128x128, warp 32x64, 2 CTAs/SM ======
// 3-stage cp.async, single barrier per iter.
// MODE 0: A=d_S (K=256),  B=d_W2p:  d_G = cnt>0 ? acc/cnt + g2b : 0
// MODE 1: A=[h|d_G] (K=2048), B=d_Wgp: out = sig(acc+gb)*h + (1-sig)*d_G
#define SLDA 36
#define AFLOATS (128 * SLDA)              // 4608
#define BFLOATS 4096                      // 2 slices x 16 nb x 128
#define SSTAGE_F (AFLOATS + BFLOATS)      // 8704 floats
#define SMEM_GEMM (3 * SSTAGE_F * 4)      // 104448 bytes -> 2 CTAs/SM
#define EPLD 68

template <int MODE>
__global__ void __launch_bounds__(256, 2) k_gemm(const float* __restrict__ hA,
                                                 const float* __restrict__ Bp,
                                                 const float* __restrict__ bias,
                                                 float* __restrict__ out) {
    extern __shared__ __align__(128) float sm[];
    constexpr int KTOT = (MODE == 1) ? 2 * D_ : GEO_;
    constexpr int NB = D_ / 8;
    constexpr int NIT = KTOT / 32;

    const int tid = threadIdx.x;
    const int wid = tid >> 5, lane = tid & 31;
    const int wm = wid >> 1, wn = wid & 1;    // 4 x 2 warp grid, 32x64 per warp
    const int m0 = blockIdx.y * 128;
    const int n0 = blockIdx.x * 128;
    const uint32_t smb = smem_u32(sm);

    const int lrow = (lane & 7) + ((lane >> 3) & 1) * 8;
    const int lcol = (lane >> 4) * 4;

    float acc[2][8][4];
    #pragma unroll
    for (int i = 0; i < 2; ++i)
        #pragma unroll
        for (int nb = 0; nb < 8; ++nb)
            #pragma unroll
            for (int q = 0; q < 4; ++q) acc[i][nb][q] = 0.f;

    auto load_async = [&](int it, int s) {
        const int k0 = it * 32;
        const uint32_t aoff = s * SSTAGE_F;
        const uint32_t boff = s * SSTAGE_F + AFLOATS;
        #pragma unroll
        for (int p = 0; p < 4; ++p) {
            int idx = tid + p * 256;
            int row = idx >> 3, c4 = idx & 7;
            const float* gp;
            if (MODE == 1)
                gp = (k0 < D_) ? hA + (size_t)(m0 + row) * D_ + k0 + c4 * 4
                               : d_G + (size_t)(m0 + row) * D_ + (k0 - D_) + c4 * 4;
            else
                gp = d_S + (size_t)(m0 + row) * GEO_ + k0 + c4 * 4;
            cp16(smb + (aoff + row * SLDA + c4 * 4) * 4, gp);
        }
        const float* bsrc = Bp + ((size_t)(k0 >> 4) * NB + (n0 >> 3)) * 128;
        #pragma unroll
        for (int p = 0; p < 4; ++p) {
            int idx = tid + p * 256;    // float4 index
            int slice = idx >> 9;
            int pos = idx & 511;
            cp16(smb + (boff + idx * 4) * 4,
                 bsrc + (size_t)slice * NB * 128 + pos * 4);
        }
        cp_commit();
    };

    auto compute = [&](int s) {
        const float* Bs = sm + s * SSTAGE_F + AFLOATS;
        const uint32_t abase = smb + (s * SSTAGE_F) * 4;
        #pragma unroll
        for (int kb2s = 0; kb2s < 2; ++kb2s) {
            uint32_t a[2][2][4];
            #pragma unroll
            for (int i = 0; i < 2; ++i)
                #pragma unroll
                for (int kss = 0; kss < 2; ++kss) {
                    int ks = kb2s * 2 + kss;
                    ldsm4(a[i][kss],
                          abase + ((wm * 32 + i * 16 + lrow) * SLDA + ks * 8 + lcol) * 4);
                }
            #pragma unroll
            for (int nb = 0; nb < 8; ++nb) {
                float4 b4 = *reinterpret_cast<const float4*>(
                    Bs + kb2s * 2048 + (wn * 8 + nb) * 128 + lane * 4);
                uint32_t b0 = __float_as_uint(b4.x), b1 = __float_as_uint(b4.y);
                uint32_t b2 = __float_as_uint(b4.z), b3 = __float_as_uint(b4.w);
                #pragma unroll
                for (int i = 0; i < 2; ++i) {
                    mma_tf32(acc[i][nb], a[i][0], b0, b1);
                    mma_tf32(acc[i][nb], a[i][1], b2, b3);
                }
            }
        }
    };

    load_async(0, 0);
    load_async(1, 1);
    #pragma unroll 1
    for (int it = 0; it < NIT; ++it) {
        if (it == NIT - 1) cp_wait<0>(); else cp_wait<1>();
        __syncthreads();
        if (it + 2 < NIT) load_async(it + 2, (it + 2) % 3);
        compute(it % 3);
    }
    __syncthreads();

    // Stage accumulators to per-warp smem
    float* ep = sm + wid * (32 * EPLD);
    const int g = lane >> 2, t4 = lane & 3;
    #pragma unroll
    for (int i = 0; i < 2; ++i)
        #pragma unroll
        for (int nb = 0; nb < 8; ++nb) {
            *reinterpret_cast<float2*>(ep + (i * 16 + g) * EPLD + nb * 8 + 2 * t4) =
                make_float2(acc[i][nb][0], acc[i][nb][1]);
            *reinterpret_cast<float2*>(ep + (i * 16 + g + 8) * EPLD + nb * 8 + 2 * t4) =
                make_float2(acc[i][nb][2], acc[i][nb][3]);
        }
    __syncwarp();

    const int m = m0 + wm * 32 + lane;
    const float* row = ep + lane * EPLD;
    const int nbase = n0 + wn * 64;

    if (MODE == 1) {
        const float* hp = hA + (size_t)m * D_ + nbase;
        const float* gp = d_G + (size_t)m * D_ + nbase;
        float* op = out + (size_t)m * D_ + nbase;
        #pragma unroll
        for (int c4 = 0; c4 < 16; ++c4) {
            float4 v = *reinterpret_cast<const float4*>(row + c4 * 4);
            float4 bb = *reinterpret_cast<const float4*>(bias + nbase + c4 * 4);
            float4 hv = *reinterpret_cast<const float4*>(hp + c4 * 4);
            float4 gv = *reinterpret_cast<const float4*>(gp + c4 * 4);
            float pr[4] = {v.x + bb.x, v.y + bb.y, v.z + bb.z, v.w + bb.w};
            float hr[4] = {hv.x, hv.y, hv.z, hv.w};
            float gr[4] = {gv.x, gv.y, gv.z, gv.w};
            float4 o;
            float* opv = &o.x;
            #pragma unroll
            for (int j = 0; j < 4; ++j) {
                float alpha = 1.f / (1.f + expf(-pr[j]));
                opv[j] = alpha * hr[j] + (1.f - alpha) * gr[j];
            }
            *reinterpret_cast<float4*>(op + c4 * 4) = o;
        }
    } else {   // MODE 0: ((Σu)@W)/c + b
        int l = m & (L_ - 1);
        int cnt = count_of(l);
        float sc = cnt > 0 ? 1.f / (float)cnt : 0.f;
        bool on = cnt > 0;
        float* gp = d_G + (size_t)m * D_ + nbase;
        #pragma unroll
        for (int c4 = 0; c4 < 16; ++c4) {
            float4 v = *reinterpret_cast<const float4*>(row + c4 * 4);
            float4 bb = *reinterpret_cast<const float4*>(bias + nbase + c4 * 4);
            float4 o;
            o.x = on ? v.x * sc + bb.x : 0.f;
            o.y = on ? v.y * sc + bb.y : 0.f;
            o.z = on ? v.z * sc + bb.z : 0.f;
            o.w = on ? v.w * sc + bb.w : 0.f;
            *reinterpret_cast<float4*>(gp + c4 * 4) = o;
        }
    }
}

extern "C" void kernel_launch(void* const* d_in, const int* in_sizes, int n_in,
                              void* d_out, int out_size) {
    const float* h   = (const float*)d_in[0];
    const float* rw  = (const float*)d_in[1];
    const float* rb  = (const float*)d_in[2];
    const float* g1w = (const float*)d_in[3];
    const float* g1b = (const float*)d_in[4];
    const float* g2w = (const float*)d_in[5];
    const float* g2b = (const float*)d_in[6];
    const float* gw  = (const float*)d_in[7];
    const float* gb  = (const float*)d_in[8];
    float* out = (float*)d_out;
    (void)in_sizes; (void)n_in; (void)out_size;

    cudaFuncSetAttribute(k_gemm<0>, cudaFuncAttributeMaxDynamicSharedMemorySize, SMEM_GEMM);
    cudaFuncSetAttribute(k_gemm<1>, cudaFuncAttributeMaxDynamicSharedMemorySize, SMEM_GEMM);
    cudaFuncSetAttribute(k_geom_gemm, cudaFuncAttributeMaxDynamicSharedMemorySize, SMEM_GEOM);
    cudaFuncSetAttribute(k_z2, cudaFuncAttributeMaxDynamicSharedMemorySize,
                         R_ * D_ * (int)sizeof(float));

    float *pS, *pG1, *pW2, *pWg;
    cudaGetSymbolAddress((void**)&pS, d_S);
    cudaGetSymbolAddress((void**)&pG1, d_G1p);
    cudaGetSymbolAddress((void**)&pW2, d_W2p);
    cudaGetSymbolAddress((void**)&pWg, d_Wgp);

    // weight prep
    k_rwT<<<R_ * D_ / 256, 256>>>(rw);
    k_repack<<<dim3(GEO_ / 128, PLUP_ / 16), 256>>>(g1w, pG1, GEO_, GEO_ / 8, PLU_);
    k_repack<<<dim3(D_ / 128, GEO_ / 16), 256>>>(g2w, pW2, D_, D_ / 8, GEO_);
    k_repack<<<dim3(D_ / 128, 2 * D_ / 16), 256>>>(gw, pWg, D_, D_ / 8, 2 * D_);

    k_z2<<<BL_ / 32, 256, R_ * D_ * sizeof(float)>>>(h, rb);

    // geometry path: plucker -> register-accumulated geom GEMM (no atomics)
    k_plucker<<<MROWS_ / 8, 256>>>();
    k_geom_gemm<<<dim3(GEO_ / 64, BL_ / 128), 256, SMEM_GEOM>>>(pG1, g1b);

    // g = (d_S/cnt) @ g2_w + b -> d_G
    k_gemm<0><<<dim3(D_ / 128, BL_ / 128), 256, SMEM_GEMM>>>(pS, pW2, g2b, nullptr);

    // gated output
    k_gemm<1><<<dim3(D_ / 128, BL_ / 128), 256, SMEM_GEMM>>>(h, pWg, gb, out);
}

// round 17
// speedup vs baseline: 1.0368x; 1.0368x over previous
#include <cuda_runtime.h>
#include <math.h>
#include <stdint.h>

#define B_ 4
#define L_ 4096
#define D_ 1024
#define R_ 16
#define PLU_ 120
#define PLUP_ 128
#define GEO_ 256
#define BL_ 16384
#define MROWS_ (6 * BL_)
#define EPS_ 1e-6f

// Scratch (static device globals: allocation-free)
__device__ float d_Z[BL_ * R_];                  // (B*L, 16)
__device__ float d_S[BL_ * GEO_];                // (B*L, 256): atomic gelu-sum
__device__ float d_P[(size_t)MROWS_ * PLUP_];    // plucker rows (cols 120..127 = 0)
__device__ float d_G[(size_t)BL_ * D_];          // g (raw fp32)
__device__ float d_G1p[PLUP_ * GEO_];            // repacked g1_w (fragment order)
__device__ float d_W2p[GEO_ * D_];               // repacked g2_w
__device__ float d_Wgp[2 * D_ * D_];             // repacked gate_w
__device__ float d_RwT[R_ * D_];                 // red_w transposed [16][1024]

__constant__ int c_off[6] = {1, 2, 4, 8, 16, 32};

__device__ __forceinline__ uint32_t smem_u32(const void* p) {
    uint32_t a;
    asm("{ .reg .u64 t; cvta.to.shared.u64 t, %1; cvt.u32.u64 %0, t; }"
        : "=r"(a) : "l"(p));
    return a;
}
__device__ __forceinline__ void cp16(uint32_t s, const void* g) {
    asm volatile("cp.async.cg.shared.global [%0], [%1], 16;" :: "r"(s), "l"(g));
}
__device__ __forceinline__ void cp_commit() { asm volatile("cp.async.commit_group;"); }
template <int N>
__device__ __forceinline__ void cp_wait() {
    asm volatile("cp.async.wait_group %0;" :: "n"(N));
}
__device__ __forceinline__ void ldsm4(uint32_t* r, uint32_t addr) {
    asm volatile("ldmatrix.sync.aligned.m8n8.x4.shared.b16 {%0,%1,%2,%3}, [%4];"
                 : "=r"(r[0]), "=r"(r[1]), "=r"(r[2]), "=r"(r[3]) : "r"(addr));
}
__device__ __forceinline__ void mma_tf32(float* d, const uint32_t* a,
                                         uint32_t b0, uint32_t b1) {
    asm volatile(
        "mma.sync.aligned.m16n8k8.row.col.f32.tf32.tf32.f32 "
        "{%0,%1,%2,%3}, {%4,%5,%6,%7}, {%8,%9}, {%0,%1,%2,%3};"
        : "+f"(d[0]), "+f"(d[1]), "+f"(d[2]), "+f"(d[3])
        : "r"(a[0]), "r"(a[1]), "r"(a[2]), "r"(a[3]), "r"(b0), "r"(b1));
}
__device__ __forceinline__ float gelu_exact(float x) {
    return 0.5f * x * (1.f + erff(x * 0.7071067811865476f));
}
__device__ __forceinline__ int count_of(int l) {
    return (l >= 1) + (l >= 2) + (l >= 4) + (l >= 8) + (l >= 16) + (l >= 32);
}

// ---------------- transpose red_w -> d_RwT[16][1024] ----------------
__global__ void k_rwT(const float* __restrict__ rw) {
    int i = blockIdx.x * 256 + threadIdx.x;   // 16384
    int d = i >> 4, r = i & 15;
    d_RwT[r * D_ + d] = rw[d * R_ + r];
}

// ------- z = h @ red_w + red_b (warp per token, 4 tokens/warp) -------
__global__ void k_z2(const float* __restrict__ h, const float* __restrict__ rb) {
    extern __shared__ float rwT[];            // 64KB
    int tid = threadIdx.x, wid = tid >> 5, lane = tid & 31;
    for (int i = tid * 4; i < R_ * D_; i += 1024)
        *reinterpret_cast<float4*>(rwT + i) =
            *reinterpret_cast<const float4*>(d_RwT + i);
    __syncthreads();

    #pragma unroll 1
    for (int tt = 0; tt < 4; ++tt) {
        int t = blockIdx.x * 32 + wid * 4 + tt;
        float acc[16];
        #pragma unroll
        for (int r = 0; r < 16; ++r) acc[r] = 0.f;
        const float* hrow = h + (size_t)t * D_;
        #pragma unroll
        for (int it = 0; it < 8; ++it) {
            float4 hv = *reinterpret_cast<const float4*>(hrow + it * 128 + lane * 4);
            #pragma unroll
            for (int r = 0; r < 16; ++r) {
                float4 wv = *reinterpret_cast<const float4*>(
                    rwT + r * D_ + it * 128 + lane * 4);
                acc[r] += hv.x * wv.x + hv.y * wv.y + hv.z * wv.z + hv.w * wv.w;
            }
        }
        #pragma unroll
        for (int r = 0; r < 16; ++r)
            #pragma unroll
            for (int o = 16; o > 0; o >>= 1)
                acc[r] += __shfl_xor_sync(0xffffffffu, acc[r], o);
        if (lane == 0) {
            #pragma unroll
            for (int r = 0; r < 16; ++r) d_Z[t * R_ + r] = acc[r] + rb[r];
        }
    }
}

// ---------------- zero d_S ----------------
__global__ void k_zeroS() {
    int i = blockIdx.x * 256 + threadIdx.x;
    *reinterpret_cast<float4*>(d_S + (size_t)i * 4) = make_float4(0.f, 0.f, 0.f, 0.f);
}

// ------ repack weight [K][N] -> fragment order [K/16][N/8][lane][slot] ------
__global__ void k_repack(const float* __restrict__ src, float* __restrict__ dst,
                         int N, int NB, int Kvalid) {
    __shared__ float tile[16 * 132];
    int tid = threadIdx.x;
    int k0 = blockIdx.y * 16;
    int n0 = blockIdx.x * 128;
    #pragma unroll
    for (int p = 0; p < 8; ++p) {
        int idx = tid + p * 256;              // 2048 = 16 x 128
        int kr = idx >> 7, nn = idx & 127;
        tile[kr * 132 + nn] = (k0 + kr < Kvalid)
            ? src[(size_t)(k0 + kr) * N + n0 + nn] : 0.f;
    }
    __syncthreads();
    size_t base = ((size_t)blockIdx.y * NB + (n0 >> 3)) * 128;
    #pragma unroll
    for (int p = 0; p < 8; ++p) {
        int idx = tid + p * 256;
        int s = idx & 3;
        int l = (idx >> 2) & 31;
        int nbL = idx >> 7;
        int kr = ((s >> 1) << 3) + (l & 3) + ((s & 1) << 2);
        int nn = nbL * 8 + (l >> 2);
        dst[base + idx] = tile[kr * 132 + nn];
    }
}

// ---------------- plucker rows: d_P[di*BL + t][0:128] ----------------
__global__ void k_plucker() {
    int wid = threadIdx.x >> 5, lane = threadIdx.x & 31;
    int ridx = blockIdx.x * 8 + wid;
    int di = ridx / BL_;
    int t = ridx - di * BL_;
    int l = t & (L_ - 1);
    int delta = c_off[di];
    float* dst = d_P + (size_t)ridx * PLUP_;
    if (l < delta) {                       // warp-uniform branch
        #pragma unroll
        for (int q = 0; q < 4; ++q) dst[lane + q * 32] = 0.f;
        return;
    }
    int tp = t - delta;
    float w = (lane < 16) ? d_Z[tp * R_ + lane] : d_Z[t * R_ + lane - 16];
    float p[4];
    float sq = 0.f;
    #pragma unroll
    for (int q = 0; q < 4; ++q) {
        int k = lane + q * 32;
        int kc = (k < PLU_) ? k : 0;
        int kk = kc, i = 0, len = R_ - 1;
        while (kk >= len) { kk -= len; i++; len--; }
        int j = i + 1 + kk;
        float ui = __shfl_sync(0xffffffffu, w, i);
        float uj = __shfl_sync(0xffffffffu, w, j);
        float vi = __shfl_sync(0xffffffffu, w, 16 + i);
        float vj = __shfl_sync(0xffffffffu, w, 16 + j);
        float val = (k < PLU_) ? (ui * vj - uj * vi) : 0.f;
        p[q] = val;
        sq += val * val;
    }
    #pragma unroll
    for (int o = 16; o > 0; o >>= 1) sq += __shfl_xor_sync(0xffffffffu, sq, o);
    float inv = 1.f / fmaxf(sqrtf(sq), EPS_);
    #pragma unroll
    for (int q = 0; q < 4; ++q) dst[lane + q * 32] = p[q] * inv;
}

// ====== explicit-mma tf32 GEMM: block 128x128, warp 32x64, 2 CTAs/SM ======
// MODE 0: A=d_S (K=256),  B=d_W2p:  d_G = cnt>0 ? acc/cnt + g2b : 0
// MODE 1: A=[h|d_G] (K=2048), B=d_Wgp: out = sig(acc+gb)*h + (1-sig)*d_G
// MODE 2: A=d_P (K=128),  B=d_G1p (NG=256): atomicAdd(d_S, masked gelu(acc+g1b))
#define SLDA 36
#define AFLOATS (128 * SLDA)              // 4608
#define BFLOATS 4096                      // 2 slices x 16 nb x 128
#define SSTAGE_F (AFLOATS + BFLOATS)      // 8704 floats
#define SMEM_GEMM (2 * SSTAGE_F * 4)      // 69632 bytes -> 2 CTAs/SM
#define EPLD 68

template <int MODE>
__global__ void __launch_bounds__(256, 2) k_gemm(const float* __restrict__ hA,
                                                 const float* __restrict__ Bp,
                                                 const float* __restrict__ bias,
                                                 float* __restrict__ out) {
    extern __shared__ __align__(128) float sm[];
    constexpr int KTOT = (MODE == 1) ? 2 * D_ : (MODE == 0 ? GEO_ : PLUP_);
    constexpr int NG = (MODE == 2) ? GEO_ : D_;
    constexpr int NB = NG / 8;
    constexpr int NIT = KTOT / 32;

    const int tid = threadIdx.x;
    const int wid = tid >> 5, lane = tid & 31;
    const int wm = wid >> 1, wn = wid & 1;    // 4 x 2 warp grid, 32x64 per warp
    const int m0 = blockIdx.y * 128;
    const int n0 = blockIdx.x * 128;
    const uint32_t smb = smem_u32(sm);

    // ldmatrix lane address components (A-tile row/col units)
    const int lrow = (lane & 7) + ((lane >> 3) & 1) * 8;
    const int lcol = (lane >> 4) * 4;

    float acc[2][8][4];
    #pragma unroll
    for (int i = 0; i < 2; ++i)
        #pragma unroll
        for (int nb = 0; nb < 8; ++nb)
            #pragma unroll
            for (int q = 0; q < 4; ++q) acc[i][nb][q] = 0.f;

    auto load_async = [&](int it, int s) {
        const int k0 = it * 32;
        const uint32_t aoff = s * SSTAGE_F;
        const uint32_t boff = s * SSTAGE_F + AFLOATS;
        #pragma unroll
        for (int p = 0; p < 4; ++p) {
            int idx = tid + p * 256;
            int row = idx >> 3, c4 = idx & 7;
            const float* gp;
            if (MODE == 1)
                gp = (k0 < D_) ? hA + (size_t)(m0 + row) * D_ + k0 + c4 * 4
                               : d_G + (size_t)(m0 + row) * D_ + (k0 - D_) + c4 * 4;
            else if (MODE == 0)
                gp = d_S + (size_t)(m0 + row) * GEO_ + k0 + c4 * 4;
            else
                gp = d_P + (size_t)(m0 + row) * PLUP_ + k0 + c4 * 4;
            cp16(smb + (aoff + row * SLDA + c4 * 4) * 4, gp);
        }
        const float* bsrc = Bp + ((size_t)(k0 >> 4) * NB + (n0 >> 3)) * 128;
        #pragma unroll
        for (int p = 0; p < 4; ++p) {
            int idx = tid + p * 256;    // float4 index
            int slice = idx >> 9;
            int pos = idx & 511;
            cp16(smb + (boff + idx * 4) * 4,
                 bsrc + (size_t)slice * NB * 128 + pos * 4);
        }
        cp_commit();
    };

    auto compute = [&](int s) {
        const float* Bs = sm + s * SSTAGE_F + AFLOATS;
        const uint32_t abase = smb + (s * SSTAGE_F) * 4;
        #pragma unroll
        for (int kb2s = 0; kb2s < 2; ++kb2s) {
            uint32_t a[2][2][4];
            #pragma unroll
            for (int i = 0; i < 2; ++i)
                #pragma unroll
                for (int kss = 0; kss < 2; ++kss) {
                    int ks = kb2s * 2 + kss;
                    ldsm4(a[i][kss],
                          abase + ((wm * 32 + i * 16 + lrow) * SLDA + ks * 8 + lcol) * 4);
                }
            #pragma unroll
            for (int nb = 0; nb < 8; ++nb) {
                float4 b4 = *reinterpret_cast<const float4*>(
                    Bs + kb2s * 2048 + (wn * 8 + nb) * 128 + lane * 4);
                uint32_t b0 = __float_as_uint(b4.x), b1 = __float_as_uint(b4.y);
                uint32_t b2 = __float_as_uint(b4.z), b3 = __float_as_uint(b4.w);
                #pragma unroll
                for (int i = 0; i < 2; ++i) {
                    mma_tf32(acc[i][nb], a[i][0], b0, b1);
                    mma_tf32(acc[i][nb], a[i][1], b2, b3);
                }
            }
        }
    };

    load_async(0, 0);
    for (int it = 0; it < NIT; ++it) {
        int cur = it & 1;
        if (it + 1 < NIT) {
            load_async(it + 1, 1 - cur);
            cp_wait<1>();
        } else {
            cp_wait<0>();
        }
        __syncthreads();
        compute(cur);
        __syncthreads();
    }

    if (MODE == 2) {
        // Direct from regs: masked gelu(acc + g1b) atomically into d_S[t][n].
        const int g = lane >> 2, t4 = lane & 3;
        #pragma unroll
        for (int i = 0; i < 2; ++i) {
            #pragma unroll
            for (int half = 0; half < 2; ++half) {
                int mrow = m0 + wm * 32 + i * 16 + g + half * 8;
                int di = mrow / BL_;
                int t = mrow - di * BL_;
                int l = t & (L_ - 1);
                bool on = l >= c_off[di];
                float* srow = d_S + (size_t)t * GEO_;
                if (on) {
                    #pragma unroll
                    for (int nb = 0; nb < 8; ++nb) {
                        int n = n0 + wn * 64 + nb * 8 + t4 * 2;
                        atomicAdd(srow + n,
                                  gelu_exact(acc[i][nb][half * 2 + 0] + bias[n]));
                        atomicAdd(srow + n + 1,
                                  gelu_exact(acc[i][nb][half * 2 + 1] + bias[n + 1]));
                    }
                }
            }
        }
        return;
    }

    // Stage accumulators to per-warp smem
    float* ep = sm + wid * (32 * EPLD);
    const int g = lane >> 2, t4 = lane & 3;
    #pragma unroll
    for (int i = 0; i < 2; ++i)
        #pragma unroll
        for (int nb = 0; nb < 8; ++nb) {
            *reinterpret_cast<float2*>(ep + (i * 16 + g) * EPLD + nb * 8 + 2 * t4) =
                make_float2(acc[i][nb][0], acc[i][nb][1]);
            *reinterpret_cast<float2*>(ep + (i * 16 + g + 8) * EPLD + nb * 8 + 2 * t4) =
                make_float2(acc[i][nb][2], acc[i][nb][3]);
        }
    __syncwarp();

    const int m = m0 + wm * 32 + lane;
    const float* row = ep + lane * EPLD;
    const int nbase = n0 + wn * 64;

    if (MODE == 1) {
        const float* hp = hA + (size_t)m * D_ + nbase;
        const float* gp = d_G + (size_t)m * D_ + nbase;
        float* op = out + (size_t)m * D_ + nbase;
        #pragma unroll
        for (int c4 = 0; c4 < 16; ++c4) {
            float4 v = *reinterpret_cast<const float4*>(row + c4 * 4);
            float4 bb = *reinterpret_cast<const float4*>(bias + nbase + c4 * 4);
            float4 hv = *reinterpret_cast<const float4*>(hp + c4 * 4);
            float4 gv = *reinterpret_cast<const float4*>(gp + c4 * 4);
            float pr[4] = {v.x + bb.x, v.y + bb.y, v.z + bb.z, v.w + bb.w};
            float hr[4] = {hv.x, hv.y, hv.z, hv.w};
            float gr[4] = {gv.x, gv.y, gv.z, gv.w};
            float4 o;
            float* opv = &o.x;
            #pragma unroll
            for (int j = 0; j < 4; ++j) {
                float alpha = 1.f / (1.f + expf(-pr[j]));
                opv[j] = alpha * hr[j] + (1.f - alpha) * gr[j];
            }
            *reinterpret_cast<float4*>(op + c4 * 4) = o;
        }
    } else {   // MODE 0: divide by count here ((Σu)@W / c == (Σu/c)@W)
        int l = m & (L_ - 1);
        int cnt = count_of(l);
        float sc = cnt > 0 ? 1.f / (float)cnt : 0.f;
        bool on = cnt > 0;
        float* gp = d_G + (size_t)m * D_ + nbase;
        #pragma unroll
        for (int c4 = 0; c4 < 16; ++c4) {
            float4 v = *reinterpret_cast<const float4*>(row + c4 * 4);
            float4 bb = *reinterpret_cast<const float4*>(bias + nbase + c4 * 4);
            float4 o;
            o.x = on ? v.x * sc + bb.x : 0.f;
            o.y = on ? v.y * sc + bb.y : 0.f;
            o.z = on ? v.z * sc + bb.z : 0.f;
            o.w = on ? v.w * sc + bb.w : 0.f;
            *reinterpret_cast<float4*>(gp + c4 * 4) = o;
        }
    }
}

extern "C" void kernel_launch(void* const* d_in, const int* in_sizes, int n_in,
                              void* d_out, int out_size) {
    const float* h   = (const float*)d_in[0];
    const float* rw  = (const float*)d_in[1];
    const float* rb  = (const float*)d_in[2];
    const float* g1w = (const float*)d_in[3];
    const float* g1b = (const float*)d_in[4];
    const float* g2w = (const float*)d_in[5];
    const float* g2b = (const float*)d_in[6];
    const float* gw  = (const float*)d_in[7];
    const float* gb  = (const float*)d_in[8];
    float* out = (float*)d_out;
    (void)in_sizes; (void)n_in; (void)out_size;

    cudaFuncSetAttribute(k_gemm<0>, cudaFuncAttributeMaxDynamicSharedMemorySize, SMEM_GEMM);
    cudaFuncSetAttribute(k_gemm<1>, cudaFuncAttributeMaxDynamicSharedMemorySize, SMEM_GEMM);
    cudaFuncSetAttribute(k_gemm<2>, cudaFuncAttributeMaxDynamicSharedMemorySize, SMEM_GEMM);
    cudaFuncSetAttribute(k_z2, cudaFuncAttributeMaxDynamicSharedMemorySize,
                         R_ * D_ * (int)sizeof(float));

    float *pP, *pS, *pG1, *pW2, *pWg;
    cudaGetSymbolAddress((void**)&pP, d_P);
    cudaGetSymbolAddress((void**)&pS, d_S);
    cudaGetSymbolAddress((void**)&pG1, d_G1p);
    cudaGetSymbolAddress((void**)&pW2, d_W2p);
    cudaGetSymbolAddress((void**)&pWg, d_Wgp);

    // weight prep
    k_rwT<<<R_ * D_ / 256, 256>>>(rw);
    k_repack<<<dim3(GEO_ / 128, PLUP_ / 16), 256>>>(g1w, pG1, GEO_, GEO_ / 8, PLU_);
    k_repack<<<dim3(D_ / 128, GEO_ / 16), 256>>>(g2w, pW2, D_, D_ / 8, GEO_);
    k_repack<<<dim3(D_ / 128, 2 * D_ / 16), 256>>>(gw, pWg, D_, D_ / 8, 2 * D_);

    k_z2<<<BL_ / 32, 256, R_ * D_ * sizeof(float)>>>(h, rb);
    k_zeroS<<<BL_ * GEO_ / 1024, 256>>>();

    // geometry path: plucker -> GEMM with fused gelu+mask+atomic-reduce into d_S
    k_plucker<<<MROWS_ / 8, 256>>>();
    k_gemm<2><<<dim3(GEO_ / 128, MROWS_ / 128), 256, SMEM_GEMM>>>(pP, pG1, g1b, nullptr);

    // g = (d_S/cnt) @ g2_w + b -> d_G
    k_gemm<0><<<dim3(D_ / 128, BL_ / 128), 256, SMEM_GEMM>>>(pS, pW2, g2b, nullptr);

    // gated output
    k_gemm<1><<<dim3(D_ / 128, BL_ / 128), 256, SMEM_GEMM>>>(h, pWg, gb, out);
}